// round 5
// baseline (speedup 1.0000x reference)
#include <cuda_runtime.h>
#include <cuda_bf16.h>
#include <cstdint>

// BFPActivation3D: block floating-point quantization over channel blocks.
// Shapes (fixed by the problem): activations [N=8, C=64, D=32, H=64, W=64] fp32,
// mantissa = 7, blk = 16. Blocks run along C at stride S = D*H*W.
//
// Per block of 16 channel values x_c at one spatial position:
//   maxabs = max |x_c|
//   se     = floor(log2(maxabs))            (== frexp exponent - 1)
//   quantum = 2^(se - (mantissa-1)) = 2^(se-6)
//   q_c = clip(rint(x_c / quantum), -127, 127) * quantum
//   all-zero block -> 0
//
// All scales are exact powers of two, so multiply-by-inverse is exact and the
// result matches the JAX reference to rounding identity (rintf = half-to-even,
// same as jnp.round).

namespace {
constexpr int N_      = 8;
constexpr int C_      = 64;
constexpr int S_      = 32 * 64 * 64;   // D*H*W = 131072 (spatial size)
constexpr int BLK     = 16;             // channels per block
constexpr int NBLK    = C_ / BLK;       // 4
constexpr int S4      = S_ / 4;         // float4 positions per (n, cblk) = 32768
constexpr int THREADS = 256;
constexpr int TOTAL_T = N_ * NBLK * S4; // 1,048,576 threads
}

__global__ __launch_bounds__(THREADS, 2)
void bfp3d_kernel(const float* __restrict__ in, float* __restrict__ out) {
    const int t = blockIdx.x * THREADS + threadIdx.x;
    // t -> (n, cblk, s4). S4 = 2^15, NBLK = 4.
    const int s4   = t & (S4 - 1);
    const int cblk = (t >> 15) & (NBLK - 1);
    const int n    = t >> 17;

    const int base = (n * C_ + cblk * BLK) * S_ + s4 * 4;   // < 2^27, int ok
    const float4* __restrict__ ip = reinterpret_cast<const float4*>(in + base);
    float4* __restrict__ op = reinterpret_cast<float4*>(out + base);

    // 16 strided float4 loads: across a warp each is a contiguous 512B segment
    // (perfectly coalesced); per-thread MLP = 16 hides DRAM latency.
    float x[4][BLK];   // [lane within float4][channel]
    #pragma unroll
    for (int c = 0; c < BLK; c++) {
        float4 v = ip[c * S4];
        x[0][c] = v.x; x[1][c] = v.y; x[2][c] = v.z; x[3][c] = v.w;
    }

    #pragma unroll
    for (int l = 0; l < 4; l++) {
        // blockwise max-abs
        float m = fabsf(x[l][0]);
        #pragma unroll
        for (int c = 1; c < BLK; c++) m = fmaxf(m, fabsf(x[l][c]));

        // shared exponent = floor(log2(m)) for normal m (exact for this data)
        const int se = (int)((__float_as_uint(m) >> 23) & 0xFFu) - 127;

        // exact power-of-two scales (integer exponent -> exact construction)
        const float rscale  = ldexpf(1.0f, 6 - se);   // 1/quantum
        const float quantum = ldexpf(1.0f, se - 6);

        const bool nz = (m > 0.0f);
        #pragma unroll
        for (int c = 0; c < BLK; c++) {
            float q = rintf(x[l][c] * rscale);          // half-to-even == jnp.round
            q = fminf(fmaxf(q, -127.0f), 127.0f);
            q *= quantum;
            x[l][c] = nz ? q : 0.0f;
        }
    }

    #pragma unroll
    for (int c = 0; c < BLK; c++) {
        float4 v;
        v.x = x[0][c]; v.y = x[1][c]; v.z = x[2][c]; v.w = x[3][c];
        op[c * S4] = v;
    }
}

extern "C" void kernel_launch(void* const* d_in, const int* in_sizes, int n_in,
                              void* d_out, int out_size) {
    const float* in = (const float*)d_in[0];   // activations, 67,108,864 floats
    float* out = (float*)d_out;
    (void)in_sizes; (void)n_in; (void)out_size;   // mantissa=7, blk=16 fixed

    bfp3d_kernel<<<TOTAL_T / THREADS, THREADS>>>(in, out);
}

// round 7
// speedup vs baseline: 1.0023x; 1.0023x over previous
#include <cuda_runtime.h>
#include <cuda_bf16.h>
#include <cstdint>

// BFPActivation3D: block floating-point quantization over channel blocks.
// Shapes (fixed by the problem): activations [N=8, C=64, D=32, H=64, W=64] fp32,
// mantissa = 7, blk = 16. Blocks run along C at stride S = D*H*W.
//
// Per block of 16 channel values x_c at one spatial position:
//   maxabs = max |x_c|
//   se     = floor(log2(maxabs))            (== frexp exponent - 1)
//   quantum = 2^(se - (mantissa-1)) = 2^(se-6)
//   q_c = clip(rint(x_c / quantum), -127, 127) * quantum
//   all-zero block -> 0
//
// All scales are exact powers of two, so multiply-by-inverse is exact and the
// result matches the JAX reference to rounding identity (rintf = half-to-even,
// same as jnp.round). Verified rel_err == 0.0 on hardware (R5).

namespace {
constexpr int N_      = 8;
constexpr int C_      = 64;
constexpr int S_      = 32 * 64 * 64;   // D*H*W = 131072 (spatial size)
constexpr int BLK     = 16;             // channels per block
constexpr int NBLK    = C_ / BLK;       // 4
constexpr int S4      = S_ / 4;         // float4 positions per (n, cblk) = 32768
constexpr int THREADS = 256;
constexpr int TOTAL_T = N_ * NBLK * S4; // 1,048,576 threads
}

// R5 post-mortem: regs=83 -> 3 CTAs fit in the 64K RF; the old bound of 2
// capped occupancy at 21% and left DRAM at 80%. Bound 3 => 24 warps/SM.
__global__ __launch_bounds__(THREADS, 3)
void bfp3d_kernel(const float* __restrict__ in, float* __restrict__ out) {
    const int t = blockIdx.x * THREADS + threadIdx.x;
    // t -> (n, cblk, s4). S4 = 2^15, NBLK = 4.
    const int s4   = t & (S4 - 1);
    const int cblk = (t >> 15) & (NBLK - 1);
    const int n    = t >> 17;

    const int base = (n * C_ + cblk * BLK) * S_ + s4 * 4;   // < 2^27, int ok
    const float4* __restrict__ ip = reinterpret_cast<const float4*>(in + base);
    float4* __restrict__ op = reinterpret_cast<float4*>(out + base);

    // 16 strided float4 loads: across a warp each is a contiguous 512B segment
    // (perfectly coalesced); per-thread MLP = 16 hides DRAM latency.
    // Streaming (evict-first) hint: data is touched exactly once.
    float x[4][BLK];   // [lane within float4][channel]
    #pragma unroll
    for (int c = 0; c < BLK; c++) {
        float4 v = __ldcs(ip + c * S4);
        x[0][c] = v.x; x[1][c] = v.y; x[2][c] = v.z; x[3][c] = v.w;
    }

    #pragma unroll
    for (int l = 0; l < 4; l++) {
        // blockwise max-abs
        float m = fabsf(x[l][0]);
        #pragma unroll
        for (int c = 1; c < BLK; c++) m = fmaxf(m, fabsf(x[l][c]));

        // shared exponent = floor(log2(m)) for normal m (exact for this data)
        const int se = (int)((__float_as_uint(m) >> 23) & 0xFFu) - 127;

        // exact power-of-two scales (integer exponent -> exact construction)
        const float rscale  = ldexpf(1.0f, 6 - se);   // 1/quantum
        const float quantum = ldexpf(1.0f, se - 6);

        const bool nz = (m > 0.0f);
        #pragma unroll
        for (int c = 0; c < BLK; c++) {
            float q = rintf(x[l][c] * rscale);          // half-to-even == jnp.round
            q = fminf(fmaxf(q, -127.0f), 127.0f);
            q *= quantum;
            x[l][c] = nz ? q : 0.0f;
        }
    }

    #pragma unroll
    for (int c = 0; c < BLK; c++) {
        float4 v;
        v.x = x[0][c]; v.y = x[1][c]; v.z = x[2][c]; v.w = x[3][c];
        __stcs(op + c * S4, v);   // streaming store: no reuse, evict first
    }
}

extern "C" void kernel_launch(void* const* d_in, const int* in_sizes, int n_in,
                              void* d_out, int out_size) {
    const float* in = (const float*)d_in[0];   // activations, 67,108,864 floats
    float* out = (float*)d_out;
    (void)in_sizes; (void)n_in; (void)out_size;   // mantissa=7, blk=16 fixed

    bfp3d_kernel<<<TOTAL_T / THREADS, THREADS>>>(in, out);
}